// round 17
// baseline (speedup 1.0000x reference)
#include <cuda_runtime.h>
#include <cuda_bf16.h>
#include <cstdint>

#define BATCHN 512
#define DIM    512
#define NCLS   1000
#define MEMSZ  200
#define KPOS   50
#define KNEG   20
#define INV_TEMP (1.0f/0.07f)
#define MARGIN 0.5f

#define NMEM  (NCLS*KNEG)        // 20000 neg rows (c,k)
#define NTOT  (NMEM + BATCHN)    // 20512 (+ f rows)
#define NPAD  20608              // 161 * 128
#define NGEMM 644                // 161 ntiles * 4 mtiles

// ---------------- GEMM config (MT=128, NT=128 best known) ----------------
#define MT 128
#define NT 128
#define KT 64
#define NSTAGE 3
#define SMEM_A_BYTES (MT*KT*2)   // 16384
#define SMEM_B_BYTES (NT*KT*2)   // 16384
#define SMEM_TOTAL (NSTAGE*(SMEM_A_BYTES+SMEM_B_BYTES))  // 98304

// ---------------- device scratch (no runtime alloc allowed) ----------------
__device__ __align__(256) float         g_fnorm[BATCHN*DIM];      // normalized f (fp32)
__device__ __align__(256) __nv_bfloat16 g_fb[BATCHN*DIM];         // normalized f (bf16)
__device__ __align__(256) __nv_bfloat16 g_bmat[(size_t)NPAD*DIM]; // packed B matrix (bf16) ~21MB
__device__ int   g_rank[BATCHN], g_gsz[BATCHN], g_fi[BATCHN];
// override table: 0 = none, else sample_idx+1. Statically zero-initialized;
// phase 3 resets the <=512 touched entries after each use (graph-replay safe).
__device__ int   g_ov[NCLS*64];
__device__ float g_all[BATCHN], g_hsum[BATCHN], g_hcnt[BATCHN];
__device__ float g_pbsum[BATCHN], g_pbcnt[BATCHN];
// persistent-kernel grid barrier counter (zero-init; reset by block 0 at end)
__device__ unsigned int g_bar;

__device__ __forceinline__ void mma_bf16(float c[4], const uint32_t a[4], uint32_t b0, uint32_t b1)
{
    asm volatile(
        "mma.sync.aligned.m16n8k16.row.col.f32.bf16.bf16.f32 "
        "{%0,%1,%2,%3},{%4,%5,%6,%7},{%8,%9},{%0,%1,%2,%3};"
        : "+f"(c[0]), "+f"(c[1]), "+f"(c[2]), "+f"(c[3])
        : "r"(a[0]), "r"(a[1]), "r"(a[2]), "r"(a[3]), "r"(b0), "r"(b1));
}

// grid barrier: all-thread release fence, tid0 arrive + spin on monotonic counter
__device__ __forceinline__ void grid_arrive_wait(unsigned int target)
{
    __threadfence();
    __syncthreads();
    if (threadIdx.x == 0) {
        atomicAdd(&g_bar, 1u);
        while (atomicAdd(&g_bar, 0u) < target) __nanosleep(64);
    }
    __syncthreads();
}

// ================= persistent mega-kernel: all phases, one launch =================
extern "C" __global__ void __launch_bounds__(256, 2)
k_mega(const float* __restrict__ feat, const int* __restrict__ labels,
       const float* __restrict__ bank, const int* __restrict__ memptr,
       float* __restrict__ out)
{
    extern __shared__ char smem[];
    const int t   = threadIdx.x;       // 256
    const int nb  = gridDim.x;         // 2 * numSMs (all co-resident)
    const int b0  = blockIdx.x;

    // ============ Phase 0: L2-normalize (512 rows) + setup (16 chunks of 32) ============
    for (int u = b0; u < BATCHN + 16; u += nb) {
        __syncthreads();               // smem reuse guard
        if (u < BATCHN) {
            float* red = (float*)smem;
            const float* row = feat + (size_t)u*DIM;
            float v0 = row[t], v1 = row[t + 256];
            float s = v0*v0 + v1*v1;
            for (int o = 16; o; o >>= 1) s += __shfl_xor_sync(0xffffffffu, s, o);
            if ((t & 31) == 0) red[t >> 5] = s;
            __syncthreads();
            float tot = 0.f;
            #pragma unroll
            for (int w = 0; w < 8; w++) tot += red[w];
            float inv = 1.0f / fmaxf(sqrtf(tot), 1e-12f);
            float n0 = v0*inv, n1 = v1*inv;
            g_fnorm[(size_t)u*DIM + t]       = n0;
            g_fnorm[(size_t)u*DIM + t + 256] = n1;
            g_fb[(size_t)u*DIM + t]          = __float2bfloat16(n0);
            g_fb[(size_t)u*DIM + t + 256]    = __float2bfloat16(n1);
        } else {
            int sb = u - BATCHN;       // 0..15, samples [sb*32, sb*32+32)
            int* sl = (int*)smem;
            sl[t] = labels[t]; sl[t + 256] = labels[t + 256];
            if (t < 32) {
                int s = sb*32 + t;
                g_all[s] = 0.f; g_hsum[s] = 0.f; g_hcnt[s] = 0.f;
                g_pbsum[s] = 0.f; g_pbcnt[s] = 0.f;
            }
            __syncthreads();
            int s_loc = t >> 3;        // 0..31 sample within chunk
            int part  = t & 7;         // 0..7 partial scanner (64 j's each)
            int s = sb*32 + s_loc;
            int lab = sl[s];
            int r = 0, g = 0, first = BATCHN;
            int j0 = part*64;
            #pragma unroll 8
            for (int j = j0; j < j0 + 64; j++) {
                bool same = (sl[j] == lab);
                g += same;
                r += (same && j < s);
                if (same && j < first) first = j;
            }
            #pragma unroll
            for (int o = 1; o < 8; o <<= 1) {
                r += __shfl_xor_sync(0xffffffffu, r, o);
                g += __shfl_xor_sync(0xffffffffu, g, o);
                int f2 = __shfl_xor_sync(0xffffffffu, first, o);
                first = min(first, f2);
            }
            if (part == 0) {
                g_rank[s] = r; g_gsz[s] = g; g_fi[s] = first;
                int wp = (memptr[lab] + r) % MEMSZ;
                if (wp < 64) g_ov[lab*64 + wp] = s + 1;   // +1 encoding, 0 = none
            }
        }
    }
    grid_arrive_wait((unsigned)nb);

    // ============ Phase 1: materialize packed bf16 B matrix ============
    for (int u = b0; u < NPAD/4; u += nb) {
        int lr = t >> 6, l = t & 63;
        int r  = u*4 + lr;

        const float* src = nullptr;
        if (r < NMEM) {
            int c = r / KNEG, k = r - c*KNEG;
            int o = g_ov[c*64 + k];
            src = (o > 0) ? (g_fnorm + (size_t)(o - 1)*DIM)
                          : (bank + ((size_t)c*MEMSZ + k)*DIM);
        } else if (r < NTOT) {
            src = g_fnorm + (size_t)(r - NMEM)*DIM;
        }

        float4 v0, v1;
        if (src) {
            v0 = ((const float4*)src)[2*l];
            v1 = ((const float4*)src)[2*l + 1];
        } else {
            v0 = make_float4(0.f,0.f,0.f,0.f);
            v1 = v0;
        }
        __nv_bfloat162 b0p = __floats2bfloat162_rn(v0.x, v0.y);
        __nv_bfloat162 b1p = __floats2bfloat162_rn(v0.z, v0.w);
        __nv_bfloat162 b2p = __floats2bfloat162_rn(v1.x, v1.y);
        __nv_bfloat162 b3p = __floats2bfloat162_rn(v1.z, v1.w);
        uint4 pack;
        pack.x = *(const uint32_t*)&b0p;
        pack.y = *(const uint32_t*)&b1p;
        pack.z = *(const uint32_t*)&b2p;
        pack.w = *(const uint32_t*)&b3p;
        ((uint4*)(g_bmat + (size_t)r*DIM))[l] = pack;
    }
    grid_arrive_wait(2u*(unsigned)nb);

    // ============ Phase 2: GEMM tiles (644) + own-GEMV units (512) ============
    for (int u = b0; u < NGEMM + BATCHN; u += nb) {
        __syncthreads();               // smem reuse guard between units

        if (u >= NGEMM) {
            // ---------- own-GEMV unit ----------
            int i = u - NGEMM;            // 0..511
            float4* fsh = (float4*)smem;
            for (int j = t; j < DIM/4; j += 256)
                fsh[j] = ((const float4*)(g_fnorm + (size_t)i*DIM))[j];
            __syncthreads();
            int lab = labels[i];
            int w = t >> 5, lane = t & 31;
            float wsum = 0.f;
            for (int k = KNEG + w; k < KPOS; k += 8) {
                int o = g_ov[lab*64 + k];
                const float4* row = (const float4*)((o > 0)
                    ? (g_fnorm + (size_t)(o - 1)*DIM)
                    : (bank + ((size_t)lab*MEMSZ + k)*DIM));
                float s = 0.f;
                #pragma unroll
                for (int c = 0; c < 4; c++) {
                    float4 a = row[lane + c*32], b = fsh[lane + c*32];
                    s += a.x*b.x + a.y*b.y + a.z*b.z + a.w*b.w;
                }
                for (int off = 16; off; off >>= 1) s += __shfl_xor_sync(0xffffffffu, s, off);
                wsum += s;
            }
            if (lane == 0) atomicAdd(&g_pbsum[i], wsum * INV_TEMP);
            continue;
        }

        // ---------- GEMM tile: u = ntile*4 + mtile ----------
        uint32_t saA = (uint32_t)__cvta_generic_to_shared(smem);
        uint32_t saB = saA + NSTAGE*SMEM_A_BYTES;

        const int ntile = u >> 2;
        const int mtile = u & 3;
        const int mbase = mtile*MT, nbase = ntile*NT;
        const int wid = t >> 5, lane = t & 31;
        const int wm = wid >> 1, wn = wid & 1;  // 4 x 2 warp grid, warp tile 32x64

        auto loadA = [&](int stage, int kbase) {
            #pragma unroll
            for (int i = 0; i < 4; i++) {
                int idx = t + i*256;
                int row = idx >> 3, cc = idx & 7;
                const void* g = g_fb + (size_t)(mbase + row)*DIM + kbase + cc*8;
                uint32_t d = saA + stage*SMEM_A_BYTES + row*128 + ((cc*16) ^ ((row & 7) << 4));
                asm volatile("cp.async.cg.shared.global [%0], [%1], 16;" :: "r"(d), "l"(g));
            }
        };
        auto loadB = [&](int stage, int kbase) {
            #pragma unroll
            for (int i = 0; i < 4; i++) {
                int idx = t + i*256;
                int row = idx >> 3, cc = idx & 7;
                const void* g = g_bmat + (size_t)(nbase + row)*DIM + kbase + cc*8;
                uint32_t d = saB + stage*SMEM_B_BYTES + row*128 + ((cc*16) ^ ((row & 7) << 4));
                asm volatile("cp.async.cg.shared.global [%0], [%1], 16;" :: "r"(d), "l"(g));
            }
        };

        float acc[2][8][4];
        #pragma unroll
        for (int a = 0; a < 2; a++)
            #pragma unroll
            for (int b = 0; b < 8; b++)
                #pragma unroll
                for (int c = 0; c < 4; c++) acc[a][b][c] = 0.f;

        loadA(0, 0);  loadB(0, 0);  asm volatile("cp.async.commit_group;" ::: "memory");
        loadA(1, KT); loadB(1, KT); asm volatile("cp.async.commit_group;" ::: "memory");

        const int a_row  = wm*32 + (lane & 15);
        const int a_xor  = (a_row & 7) << 4;
        const int a_c8b  = ((lane >> 4) & 1) * 16;
        const int b_rin  = (lane & 7) + (((lane >> 4) & 1) << 3);
        const int b_c8b  = ((lane >> 3) & 1) * 16;

        const int NS = DIM / KT;  // 8
        for (int ks = 0; ks < NS; ks++) {
            if (ks < NS - 1) asm volatile("cp.async.wait_group 1;" ::: "memory");
            else             asm volatile("cp.async.wait_group 0;" ::: "memory");
            __syncthreads();

            if (ks + 2 < NS) {
                int st = (ks + 2) % NSTAGE;
                loadA(st, (ks + 2)*KT); loadB(st, (ks + 2)*KT);
                asm volatile("cp.async.commit_group;" ::: "memory");
            }

            uint32_t sa = saA + (ks % NSTAGE)*SMEM_A_BYTES;
            uint32_t sb = saB + (ks % NSTAGE)*SMEM_B_BYTES;

            #pragma unroll
            for (int kk = 0; kk < 4; kk++) {
                uint32_t afr[2][4];
                uint32_t bfr[4][4];
                #pragma unroll
                for (int mi = 0; mi < 2; mi++) {
                    uint32_t addr = sa + (a_row + mi*16)*128 + ((kk*32 + a_c8b) ^ a_xor);
                    asm volatile("ldmatrix.sync.aligned.m8n8.x4.shared.b16 {%0,%1,%2,%3}, [%4];"
                        : "=r"(afr[mi][0]), "=r"(afr[mi][1]), "=r"(afr[mi][2]), "=r"(afr[mi][3])
                        : "r"(addr));
                }
                #pragma unroll
                for (int np = 0; np < 4; np++) {
                    int nrow = wn*64 + np*16 + b_rin;
                    uint32_t baddr = sb + nrow*128 + ((kk*32 + b_c8b) ^ ((nrow & 7) << 4));
                    asm volatile("ldmatrix.sync.aligned.m8n8.x4.shared.b16 {%0,%1,%2,%3}, [%4];"
                        : "=r"(bfr[np][0]), "=r"(bfr[np][1]), "=r"(bfr[np][2]), "=r"(bfr[np][3])
                        : "r"(baddr));
                }
                #pragma unroll
                for (int np = 0; np < 4; np++) {
                    #pragma unroll
                    for (int mi = 0; mi < 2; mi++) {
                        mma_bf16(acc[mi][2*np],   afr[mi], bfr[np][0], bfr[np][1]);
                        mma_bf16(acc[mi][2*np+1], afr[mi], bfr[np][2], bfr[np][3]);
                    }
                }
            }
        }

        // ---------- fused epilogue ----------
        const int gid = lane >> 2, tq = lane & 3;
        int rows[4]; int lab[4]; int fi_[4]; int gsz_[4];
        #pragma unroll
        for (int mi = 0; mi < 2; mi++) {
            int r0 = mbase + wm*32 + mi*16 + gid;
            rows[2*mi] = r0; rows[2*mi+1] = r0 + 8;
        }
        #pragma unroll
        for (int q = 0; q < 4; q++) {
            lab[q]  = labels[rows[q]];
            fi_[q]  = g_fi[rows[q]];
            gsz_[q] = g_gsz[rows[q]];
        }

        float lAll[4] = {0,0,0,0}, lHS[4] = {0,0,0,0}, lHC[4] = {0,0,0,0};
        float lPS[4] = {0,0,0,0}, lPC[4] = {0,0,0,0};

        #pragma unroll
        for (int nf = 0; nf < 8; nf++) {
            int ncol0 = nbase + wn*64 + nf*8 + tq*2;
            #pragma unroll
            for (int cc = 0; cc < 2; cc++) {
                int r = ncol0 + cc;
                int type, cC = 0, lj = 0, rj = 0;
                if (r < NMEM)      { type = 0; cC = r / KNEG; }
                else if (r < NTOT) { type = 1; int j = r - NMEM; lj = labels[j]; rj = g_rank[j]; }
                else               { type = 2; }
                #pragma unroll
                for (int q = 0; q < 4; q++) {
                    float s = acc[q >> 1][nf][(q & 1)*2 + cc] * INV_TEMP;
                    if (type == 0) {
                        if (cC == lab[q]) {
                            lPS[q] += s;                 // own-class k<20: part of pos_sum
                        } else {
                            lAll[q] += s;
                            if (s > MARGIN) { lHS[q] += s; lHC[q] += 1.f; }
                        }
                    } else if (type == 1) {
                        if (lj == lab[q] && rj != fi_[q] && gsz_[q] > 1) {
                            lPS[q] += s; lPC[q] += 1.f;
                        }
                    }
                }
            }
        }

        #pragma unroll
        for (int q = 0; q < 4; q++) {
            #pragma unroll
            for (int o = 1; o <= 2; o <<= 1) {
                lAll[q] += __shfl_xor_sync(0xffffffffu, lAll[q], o);
                lHS[q]  += __shfl_xor_sync(0xffffffffu, lHS[q],  o);
                lHC[q]  += __shfl_xor_sync(0xffffffffu, lHC[q],  o);
                lPS[q]  += __shfl_xor_sync(0xffffffffu, lPS[q],  o);
                lPC[q]  += __shfl_xor_sync(0xffffffffu, lPC[q],  o);
            }
            if (tq == 0) {
                atomicAdd(&g_all[rows[q]],   lAll[q]);
                atomicAdd(&g_hsum[rows[q]],  lHS[q]);
                atomicAdd(&g_hcnt[rows[q]],  lHC[q]);
                atomicAdd(&g_pbsum[rows[q]], lPS[q]);
                atomicAdd(&g_pbcnt[rows[q]], lPC[q]);
            }
        }
    }

    // ============ Phase 3: arrive; only block 0 waits + combines ============
    __threadfence();
    __syncthreads();
    if (t == 0) atomicAdd(&g_bar, 1u);
    if (b0 != 0) return;                   // only block 0 spins -> safe counter reset
    if (t == 0) {
        while (atomicAdd(&g_bar, 0u) < 3u*(unsigned)nb) __nanosleep(64);
    }
    __syncthreads();

    {
        float part = 0.f;
        #pragma unroll
        for (int rep = 0; rep < 2; rep++) {
            int i = t + rep*256;
            int lab = labels[i];
            int wp = (memptr[lab] + g_rank[i]) % MEMSZ;
            if (wp < 64) g_ov[lab*64 + wp] = 0;   // restore all-zero invariant

            float ps = __ldcg(&g_pbsum[i]);       // includes all 50 own-class sims
            float pc = __ldcg(&g_pbcnt[i]) + (float)KPOS;
            float pl = -ps / pc;
            float hc = __ldcg(&g_hcnt[i]);
            float nl = (hc > 0.f) ? (__ldcg(&g_hsum[i]) / fmaxf(hc, 1.f))
                                  : (__ldcg(&g_all[i]) / ((float)(NCLS - 1) * (float)KNEG));
            part += pl + nl;
        }
        __shared__ float red2[8];
        for (int o = 16; o; o >>= 1) part += __shfl_xor_sync(0xffffffffu, part, o);
        if ((t & 31) == 0) red2[t >> 5] = part;
        __syncthreads();
        if (t == 0) {
            float tot = 0.f;
            #pragma unroll
            for (int w = 0; w < 8; w++) tot += red2[w];
            out[0] = tot / (float)BATCHN;
            atomicExch(&g_bar, 0u);        // reset for next graph replay
        }
    }
}

// ================= launch =================
extern "C" void kernel_launch(void* const* d_in, const int* in_sizes, int n_in,
                              void* d_out, int out_size)
{
    const float* feat   = (const float*)d_in[0];
    const int*   labels = (const int*)  d_in[1];
    const float* bank   = (const float*)d_in[2];
    const int*   mptr   = (const int*)  d_in[3];
    float* out = (float*)d_out;

    cudaFuncSetAttribute(k_mega, cudaFuncAttributeMaxDynamicSharedMemorySize, SMEM_TOTAL);

    int nsm = 148;
    cudaDeviceGetAttribute(&nsm, cudaDevAttrMultiProcessorCount, 0);

    k_mega<<<2*nsm, 256, SMEM_TOTAL>>>(feat, labels, bank, mptr, out);
}